// round 15
// baseline (speedup 1.0000x reference)
#include <cuda_runtime.h>
#include <cuda_fp16.h>

// GNNEncoder: B=8, N=10000, F_IN=128, H=128, E=160000
#define NB     8
#define NNODES 10000
#define HDIM   128
#define BH     (NB * HDIM)        // 1024
#define BH4    (BH / 4)           // 256 uint2 (4 halves) per node row
#define ROWB   2048               // node row byte stride (BH4 * 8)
#define EMAX   160000
#define ROWS   (NNODES * NB)      // 80000 gemm rows (node-major: r = n*8+b)
#define GEMMBLK 1250              // ROWS / 64
#define CSRBLK  625               // EMAX / 256
#define SMAX   256                // staged edge offsets per node
#define AGGBLK (NNODES / 2)       // 5000: 2 nodes per agg block

// ---------------- device scratch -------------------------------------------
// Invariant: d_cnt[] == 0 and d_total == 0 at entry of every kernel_launch
// (static init supplies the first call; aggLN's tail restores it each call).
__device__ uint2  d_t1[NNODES * BH4];   // fp16 x4, dinv-prescaled gather rows
__device__ float4 d_h1[NNODES * BH4];   // fp32 relu(agg1+b1): GEMM2 input
__device__ uint2  d_t2[NNODES * BH4];   // fp16 x4, dinv-prescaled
__device__ __align__(16) uint2 d_w1f[16 * 16 * 32];  // W tf32 frag [kk][ct][lane]
__device__ __align__(16) uint2 d_w2f[16 * 16 * 32];
__device__ int    d_cnt[NNODES];
__device__ int    d_beg[NNODES];
__device__ int    d_cur[NNODES];
__device__ float  d_dinv[NNODES];
__device__ int    d_csr[EMAX];          // holds src * ROWB (byte offsets)
__device__ int    d_total;

// ---------------- helpers --------------------------------------------------
__device__ __forceinline__ unsigned f2tf32(float x) {
    unsigned r;
    asm("cvt.rna.tf32.f32 %0, %1;" : "=r"(r) : "f"(x));
    return r;
}
__device__ __forceinline__ unsigned f2_to_h2(float lo, float hi) {
    unsigned r;
    asm("cvt.rn.f16x2.f32 %0, %1, %2;" : "=r"(r) : "f"(hi), "f"(lo));
    return r;
}
__device__ __forceinline__ float2 h2_to_f2(unsigned u) {
    __half2 h = *reinterpret_cast<__half2*>(&u);
    return __half22float2(h);
}
__device__ __forceinline__ unsigned hadd2u(unsigned a, unsigned b) {
    __half2 ha = *reinterpret_cast<__half2*>(&a);
    __half2 hb = *reinterpret_cast<__half2*>(&b);
    __half2 hr = __hadd2(ha, hb);
    return *reinterpret_cast<unsigned*>(&hr);
}
__device__ __forceinline__ void mma_tf32(float* c, unsigned a0, unsigned a1,
                                         unsigned a2, unsigned a3,
                                         unsigned b0, unsigned b1) {
    asm("mma.sync.aligned.m16n8k8.row.col.f32.tf32.tf32.f32 "
        "{%0,%1,%2,%3}, {%4,%5,%6,%7}, {%8,%9}, {%0,%1,%2,%3};"
        : "+f"(c[0]), "+f"(c[1]), "+f"(c[2]), "+f"(c[3])
        : "r"(a0), "r"(a1), "r"(a2), "r"(a3), "r"(b0), "r"(b1));
}
// int64 buffers hold values < 2^31 -> odd 32-bit words are all zero.
__device__ __forceinline__ int detect64(const int* __restrict__ ei) {
    return ((ei[1] | ei[3] | ei[5] | ei[7] |
             ei[9] | ei[11] | ei[13] | ei[15]) == 0) ? 2 : 1;  // word stride
}
// accumulate an fp16 pair-sum word-pair into (A, B)
__device__ __forceinline__ void accAB(float4& A, float4& B,
                                      unsigned qx, unsigned qy,
                                      unsigned rx, unsigned ry) {
    float2 f;
    f = h2_to_f2(qx); A.x += f.x; A.y += f.y;
    f = h2_to_f2(qy); A.z += f.x; A.w += f.y;
    f = h2_to_f2(rx); B.x += f.x; B.y += f.y;
    f = h2_to_f2(ry); B.z += f.x; B.w += f.y;
}

// ---------------- kernel 1: degree count + W fragment prep -----------------
__global__ void __launch_bounds__(256) countPrepKernel(const int* __restrict__ ei,
                                                       const float* __restrict__ W1,
                                                       const float* __restrict__ W2,
                                                       int E) {
    int blk = blockIdx.x;
    int t = threadIdx.x;
    if (blk < CSRBLK) {
        int e = blk * 256 + t;
        if (e < E) {
            int stride = detect64(ei);
            int dst = ei[(size_t)stride * (E + e)];
            if ((unsigned)dst < NNODES) atomicAdd(&d_cnt[dst], 1);
        }
    } else {
        int idx = (blk - CSRBLK) * 256 + t;   // 0..8191
        int kk = idx >> 9;
        int ct = (idx >> 5) & 15;
        int l = idx & 31;
        int k0 = kk * 8 + (l & 3);
        int n = ct * 8 + (l >> 2);
        uint2 v1, v2;
        v1.x = f2tf32(W1[k0 * HDIM + n]);
        v1.y = f2tf32(W1[(k0 + 4) * HDIM + n]);
        v2.x = f2tf32(W2[k0 * HDIM + n]);
        v2.y = f2tf32(W2[(k0 + 4) * HDIM + n]);
        d_w1f[idx] = v1;
        d_w2f[idx] = v2;
    }
}

// ---------------- kernel 2: CSR base offsets + dinv -------------------------
__global__ void baseKernel() {
    int n = blockIdx.x * blockDim.x + threadIdx.x;
    if (n < NNODES) {
        int c = d_cnt[n];
        int base = atomicAdd(&d_total, c);
        d_beg[n] = base;
        d_cur[n] = base;
        d_dinv[n] = rsqrtf((float)(c + 1));   // +1 for self loop
    }
}

// ---------------- tf32 MMA core over smem-staged A --------------------------
// xs[64][132]: 64 rows x 128 floats, pad 4 -> conflict-free fragment reads.
__device__ __forceinline__ void gemm_mma_smem(const float xs[64][132],
                                              const uint2* __restrict__ wf,
                                              unsigned* __restrict__ outp,
                                              int grbase, int w, int lane) {
    int tid = lane & 3;
    int gid = lane >> 2;
    int r0l = (w >> 1) * 16 + gid;
    int r1l = r0l + 8;
    int colbase = (w & 1) * 64;
    const uint2* wfh = wf + (w & 1) * 256;   // ct-half offset (8 tiles x 32)

    float c[8][4];
#pragma unroll
    for (int ct = 0; ct < 8; ct++)
#pragma unroll
        for (int j = 0; j < 4; j++) c[ct][j] = 0.f;

#pragma unroll 4
    for (int kk = 0; kk < 16; kk++) {
        int k0 = kk * 8 + tid;
        unsigned a0 = f2tf32(xs[r0l][k0]);
        unsigned a1 = f2tf32(xs[r1l][k0]);
        unsigned a2 = f2tf32(xs[r0l][k0 + 4]);
        unsigned a3 = f2tf32(xs[r1l][k0 + 4]);
        const uint2* wrow = wfh + kk * 512 + lane;
#pragma unroll
        for (int ct = 0; ct < 8; ct++) {
            uint2 b = wrow[ct * 32];
            mma_tf32(c[ct], a0, a1, a2, a3, b.x, b.y);
        }
    }

    int gr0 = grbase + r0l;
    int gr1 = grbase + r1l;
    float s0 = d_dinv[gr0 >> 3];
    float s1 = d_dinv[gr1 >> 3];
#pragma unroll
    for (int ct = 0; ct < 8; ct++) {
        int h = colbase + ct * 8 + tid * 2;
        outp[(size_t)gr0 * 64 + (h >> 1)] = f2_to_h2(c[ct][0] * s0, c[ct][1] * s0);
        outp[(size_t)gr1 * 64 + (h >> 1)] = f2_to_h2(c[ct][2] * s1, c[ct][3] * s1);
    }
}

// ---------------- kernel 3: GEMM1 (x @ W1) fused with CSR fill --------------
__global__ void __launch_bounds__(256) gemm1CsrKernel(const float4* __restrict__ x4,
                                                      const int* __restrict__ ei,
                                                      int E) {
    __shared__ float xs[64][132];
    int t = threadIdx.x;
    if (blockIdx.x < GEMMBLK) {
        int grbase = blockIdx.x * 64;
        // stage: x layout [b][n][f]; row r = n*8 + b
#pragma unroll
        for (int it = 0; it < 8; it++) {
            int e = it * 256 + t;
            int r = e >> 5, f4 = e & 31;
            int gr = grbase + r;
            float4 v = x4[((size_t)(gr & 7) * NNODES + (gr >> 3)) * 32 + f4];
            *(float4*)&xs[r][f4 * 4] = v;
        }
        __syncthreads();
        gemm_mma_smem(xs, d_w1f, (unsigned*)d_t1, grbase, t >> 5, t & 31);
    } else {
        int e = (blockIdx.x - GEMMBLK) * 256 + t;
        if (e < E) {
            int stride = detect64(ei);
            int src = ei[(size_t)stride * e];
            int dst = ei[(size_t)stride * (E + e)];
            if ((unsigned)src < NNODES && (unsigned)dst < NNODES) {
                int p = atomicAdd(&d_cur[dst], 1);
                if ((unsigned)p < EMAX) d_csr[p] = src * ROWB;  // byte offset
            }
        }
    }
}

// ---------------- kernel 5: GEMM2 (h1 @ W2) --------------------------------
__global__ void __launch_bounds__(256) gemm2Kernel() {
    __shared__ float xs[64][132];
    int t = threadIdx.x;
    int grbase = blockIdx.x * 64;
    const float4* h4 = (const float4*)d_h1;   // [r][128] contiguous
#pragma unroll
    for (int it = 0; it < 8; it++) {
        int e = it * 256 + t;
        int r = e >> 5, f4 = e & 31;
        *(float4*)&xs[r][f4 * 4] = h4[(size_t)(grbase + r) * 32 + f4];
    }
    __syncthreads();
    gemm_mma_smem(xs, d_w2f, (unsigned*)d_t2, grbase, t >> 5, t & 31);
}

// ---------------- dual-node aggregation ------------------------------------
// Block = 2 nodes. Thread t covers cols 4t..4t+3 of BOTH nodes, interleaving
// the two independent gather streams in one loop (MLP 2x, no extra syncs).
struct DualAcc { float4 A0, B0, A1, B1; };

__device__ __forceinline__ void agg_dual(const uint2* __restrict__ tin,
                                         int na, int nb, int t,
                                         const int* __restrict__ soffA,
                                         const int* __restrict__ soffB,
                                         int cntA, int cntB, int begA, int begB,
                                         float4& outA, float4& outB) {
    const char* basep = (const char*)(tin + t);
    uint2 psA = tin[(size_t)na * BH4 + t];
    uint2 psB = tin[(size_t)nb * BH4 + t];
    float2 f;
    float4 A0, B0 = {0.f, 0.f, 0.f, 0.f};
    float4 A1, B1 = {0.f, 0.f, 0.f, 0.f};
    f = h2_to_f2(psA.x); A0.x = f.x; A0.y = f.y;
    f = h2_to_f2(psA.y); A0.z = f.x; A0.w = f.y;
    f = h2_to_f2(psB.x); A1.x = f.x; A1.y = f.y;
    f = h2_to_f2(psB.y); A1.z = f.x; A1.w = f.y;

    int mA = (cntA < SMAX) ? cntA : SMAX;
    int mB = (cntB < SMAX) ? cntB : SMAX;
    int mj = ((mA < mB) ? mA : mB) & ~3;
    int e = 0;
    // joint loop: 8 independent LDGs in flight (4 per node)
    for (; e < mj; e += 4) {
        int a0 = soffA[e + 0], a1 = soffA[e + 1];
        int a2 = soffA[e + 2], a3 = soffA[e + 3];
        int b0 = soffB[e + 0], b1 = soffB[e + 1];
        int b2 = soffB[e + 2], b3 = soffB[e + 3];
        uint2 pA0 = *(const uint2*)(basep + a0);
        uint2 pA1 = *(const uint2*)(basep + a1);
        uint2 pA2 = *(const uint2*)(basep + a2);
        uint2 pA3 = *(const uint2*)(basep + a3);
        uint2 pB0 = *(const uint2*)(basep + b0);
        uint2 pB1 = *(const uint2*)(basep + b1);
        uint2 pB2 = *(const uint2*)(basep + b2);
        uint2 pB3 = *(const uint2*)(basep + b3);
        accAB(A0, B0, hadd2u(pA0.x, pA1.x), hadd2u(pA0.y, pA1.y),
                      hadd2u(pA2.x, pA3.x), hadd2u(pA2.y, pA3.y));
        accAB(A1, B1, hadd2u(pB0.x, pB1.x), hadd2u(pB0.y, pB1.y),
                      hadd2u(pB2.x, pB3.x), hadd2u(pB2.y, pB3.y));
    }
    // finish node A
    int eA = e;
    for (; eA + 2 <= mA; eA += 2) {
        uint2 p0 = *(const uint2*)(basep + soffA[eA]);
        uint2 p1 = *(const uint2*)(basep + soffA[eA + 1]);
        f = h2_to_f2(hadd2u(p0.x, p1.x)); A0.x += f.x; A0.y += f.y;
        f = h2_to_f2(hadd2u(p0.y, p1.y)); A0.z += f.x; A0.w += f.y;
    }
    if (eA < mA) {
        uint2 p = *(const uint2*)(basep + soffA[eA]);
        f = h2_to_f2(p.x); A0.x += f.x; A0.y += f.y;
        f = h2_to_f2(p.y); A0.z += f.x; A0.w += f.y;
    }
    for (int r = mA; r < cntA; r++) {            // rare overflow path
        uint2 p = *(const uint2*)(basep + d_csr[begA + r]);
        f = h2_to_f2(p.x); A0.x += f.x; A0.y += f.y;
        f = h2_to_f2(p.y); A0.z += f.x; A0.w += f.y;
    }
    // finish node B
    int eB = e;
    for (; eB + 2 <= mB; eB += 2) {
        uint2 p0 = *(const uint2*)(basep + soffB[eB]);
        uint2 p1 = *(const uint2*)(basep + soffB[eB + 1]);
        f = h2_to_f2(hadd2u(p0.x, p1.x)); A1.x += f.x; A1.y += f.y;
        f = h2_to_f2(hadd2u(p0.y, p1.y)); A1.z += f.x; A1.w += f.y;
    }
    if (eB < mB) {
        uint2 p = *(const uint2*)(basep + soffB[eB]);
        f = h2_to_f2(p.x); A1.x += f.x; A1.y += f.y;
        f = h2_to_f2(p.y); A1.z += f.x; A1.w += f.y;
    }
    for (int r = mB; r < cntB; r++) {
        uint2 p = *(const uint2*)(basep + d_csr[begB + r]);
        f = h2_to_f2(p.x); A1.x += f.x; A1.y += f.y;
        f = h2_to_f2(p.y); A1.z += f.x; A1.w += f.y;
    }
    float dA = d_dinv[na];
    float dB = d_dinv[nb];
    outA.x = (A0.x + B0.x) * dA;
    outA.y = (A0.y + B0.y) * dA;
    outA.z = (A0.z + B0.z) * dA;
    outA.w = (A0.w + B0.w) * dA;
    outB.x = (A1.x + B1.x) * dB;
    outB.y = (A1.y + B1.y) * dB;
    outB.z = (A1.z + B1.z) * dB;
    outB.w = (A1.w + B1.w) * dB;
}

// kernel 4: dual-node agg + relu + bias -> h1
__global__ void __launch_bounds__(256) aggReluKernel(const float4* __restrict__ bias4) {
    __shared__ int soffA[SMAX], soffB[SMAX];
    __shared__ int snfo[4];
    int t = threadIdx.x;
    int na = blockIdx.x * 2;
    int nb = na + 1;
    if (t < 2) { snfo[t * 2] = d_beg[na + t]; snfo[t * 2 + 1] = d_cnt[na + t]; }
    __syncthreads();
    int begA = snfo[0], cntA = snfo[1];
    int begB = snfo[2], cntB = snfo[3];
    if (t < ((cntA < SMAX) ? cntA : SMAX)) soffA[t] = d_csr[begA + t];
    if (t < ((cntB < SMAX) ? cntB : SMAX)) soffB[t] = d_csr[begB + t];
    __syncthreads();

    float4 vA, vB;
    agg_dual(d_t1, na, nb, t, soffA, soffB, cntA, cntB, begA, begB, vA, vB);
    float4 bb = bias4[t & 31];
    vA.x = fmaxf(vA.x + bb.x, 0.f);
    vA.y = fmaxf(vA.y + bb.y, 0.f);
    vA.z = fmaxf(vA.z + bb.z, 0.f);
    vA.w = fmaxf(vA.w + bb.w, 0.f);
    vB.x = fmaxf(vB.x + bb.x, 0.f);
    vB.y = fmaxf(vB.y + bb.y, 0.f);
    vB.z = fmaxf(vB.z + bb.z, 0.f);
    vB.w = fmaxf(vB.w + bb.w, 0.f);
    d_h1[(size_t)na * BH4 + t] = vA;
    d_h1[(size_t)nb * BH4 + t] = vB;
}

// kernel 6: dual-node agg + LayerNorm. Warp w owns batch-row w of both nodes.
// Tail restores the d_cnt/d_total == 0 invariant for the next replay.
__global__ void __launch_bounds__(256) aggLNKernel(const float4* __restrict__ bias4,
                                                   const float4* __restrict__ lnw4,
                                                   const float4* __restrict__ lnb4,
                                                   float4* __restrict__ out4) {
    __shared__ int soffA[SMAX], soffB[SMAX];
    __shared__ int snfo[4];
    int t = threadIdx.x;
    int lane = t & 31;
    int b = t >> 5;
    int na = blockIdx.x * 2;
    int nb = na + 1;
    if (t < 2) { snfo[t * 2] = d_beg[na + t]; snfo[t * 2 + 1] = d_cnt[na + t]; }
    __syncthreads();
    int begA = snfo[0], cntA = snfo[1];
    int begB = snfo[2], cntB = snfo[3];
    if (t < ((cntA < SMAX) ? cntA : SMAX)) soffA[t] = d_csr[begA + t];
    if (t < ((cntB < SMAX) ? cntB : SMAX)) soffB[t] = d_csr[begB + t];
    __syncthreads();

    float4 vA, vB;
    agg_dual(d_t2, na, nb, t, soffA, soffB, cntA, cntB, begA, begB, vA, vB);
    float4 bb = bias4[lane];
    float4 w = lnw4[lane];
    float4 bo = lnb4[lane];

#pragma unroll
    for (int k = 0; k < 2; k++) {
        float4 v = (k == 0) ? vA : vB;
        int n = na + k;
        v.x += bb.x; v.y += bb.y; v.z += bb.z; v.w += bb.w;

        float s = (v.x + v.y) + (v.z + v.w);
#pragma unroll
        for (int off = 16; off > 0; off >>= 1) s += __shfl_xor_sync(0xffffffffu, s, off);
        float mean = s * (1.f / 128.f);

        float4 d;
        d.x = v.x - mean; d.y = v.y - mean; d.z = v.z - mean; d.w = v.w - mean;
        float s2 = (d.x * d.x + d.y * d.y) + (d.z * d.z + d.w * d.w);
#pragma unroll
        for (int off = 16; off > 0; off >>= 1) s2 += __shfl_xor_sync(0xffffffffu, s2, off);
        float rs = rsqrtf(s2 * (1.f / 128.f) + 1e-5f);

        float4 r;
        r.x = d.x * rs * w.x + bo.x;
        r.y = d.y * rs * w.y + bo.y;
        r.z = d.z * rs * w.z + bo.z;
        r.w = d.w * rs * w.w + bo.w;
        out4[((size_t)b * NNODES + n) * 32 + lane] = r;
    }

    // restore invariant (after all agg reads of this block's d_cnt)
    __syncthreads();
    if (t < 2) d_cnt[na + t] = 0;
    if (blockIdx.x == 0 && t == 2) d_total = 0;
}

// ---------------- launch ---------------------------------------------------
extern "C" void kernel_launch(void* const* d_in, const int* in_sizes, int n_in,
                              void* d_out, int out_size) {
    const float4* x4  = (const float4*)d_in[0];
    const int*    ei  = (const int*)d_in[1];     // int32 OR int64 (auto)
    const float*  W1  = (const float*)d_in[2];
    const float4* b1  = (const float4*)d_in[3];
    const float*  W2  = (const float*)d_in[4];
    const float4* b2  = (const float4*)d_in[5];
    const float4* lnw = (const float4*)d_in[6];
    const float4* lnb = (const float4*)d_in[7];
    float4*       out = (float4*)d_out;

    int E = in_sizes[1] / 2;
    if (E > EMAX) E = EMAX;

    countPrepKernel<<<CSRBLK + 32, 256>>>(ei, W1, W2, E);
    baseKernel<<<(NNODES + 255) / 256, 256>>>();
    gemm1CsrKernel<<<GEMMBLK + CSRBLK, 256>>>(x4, ei, E);
    aggReluKernel<<<AGGBLK, 256>>>(b1);
    gemm2Kernel<<<GEMMBLK, 256>>>();
    aggLNKernel<<<AGGBLK, 256>>>(b2, lnw, lnb, out);
}

// round 16
// speedup vs baseline: 1.3614x; 1.3614x over previous
#include <cuda_runtime.h>
#include <cuda_fp16.h>

// GNNEncoder: B=8, N=10000, F_IN=128, H=128, E=160000
#define NB     8
#define NNODES 10000
#define HDIM   128
#define BH     (NB * HDIM)        // 1024
#define BH4    (BH / 4)           // 256 uint2 (4 halves) per node row
#define ROWB   2048               // node row byte stride (BH4 * 8)
#define EMAX   160000
#define ROWS   (NNODES * NB)      // 80000 gemm rows (node-major: r = n*8+b)
#define GEMMBLK 1250              // ROWS / 64
#define CSRBLK  625               // EMAX / 256
#define SMAX   256                // staged edge offsets per node

// ---------------- device scratch -------------------------------------------
// Invariant: d_cnt[] == 0 and d_total == 0 at entry of every kernel_launch
// (static init supplies the first call; aggLN's tail restores it each call).
__device__ uint2  d_t1[NNODES * BH4];   // fp16 x4, dinv-prescaled gather rows
__device__ float4 d_h1[NNODES * BH4];   // fp32 relu(agg1+b1): GEMM2 input
__device__ uint2  d_t2[NNODES * BH4];   // fp16 x4, dinv-prescaled
__device__ __align__(16) uint2 d_w1f[16 * 16 * 32];  // W tf32 frag [kk][ct][lane]
__device__ __align__(16) uint2 d_w2f[16 * 16 * 32];
__device__ int    d_cnt[NNODES];
__device__ int    d_beg[NNODES];
__device__ int    d_cur[NNODES];
__device__ float  d_dinv[NNODES];
__device__ int    d_csr[EMAX];          // holds src * ROWB (byte offsets)
__device__ int    d_total;

// ---------------- helpers --------------------------------------------------
__device__ __forceinline__ unsigned f2tf32(float x) {
    unsigned r;
    asm("cvt.rna.tf32.f32 %0, %1;" : "=r"(r) : "f"(x));
    return r;
}
__device__ __forceinline__ unsigned f2_to_h2(float lo, float hi) {
    unsigned r;
    asm("cvt.rn.f16x2.f32 %0, %1, %2;" : "=r"(r) : "f"(hi), "f"(lo));
    return r;
}
__device__ __forceinline__ float2 h2_to_f2(unsigned u) {
    __half2 h = *reinterpret_cast<__half2*>(&u);
    return __half22float2(h);
}
__device__ __forceinline__ unsigned hadd2u(unsigned a, unsigned b) {
    __half2 ha = *reinterpret_cast<__half2*>(&a);
    __half2 hb = *reinterpret_cast<__half2*>(&b);
    __half2 hr = __hadd2(ha, hb);
    return *reinterpret_cast<unsigned*>(&hr);
}
__device__ __forceinline__ void mma_tf32(float* c, unsigned a0, unsigned a1,
                                         unsigned a2, unsigned a3,
                                         unsigned b0, unsigned b1) {
    asm("mma.sync.aligned.m16n8k8.row.col.f32.tf32.tf32.f32 "
        "{%0,%1,%2,%3}, {%4,%5,%6,%7}, {%8,%9}, {%0,%1,%2,%3};"
        : "+f"(c[0]), "+f"(c[1]), "+f"(c[2]), "+f"(c[3])
        : "r"(a0), "r"(a1), "r"(a2), "r"(a3), "r"(b0), "r"(b1));
}
// int64 buffers hold values < 2^31 -> odd 32-bit words are all zero.
__device__ __forceinline__ int detect64(const int* __restrict__ ei) {
    return ((ei[1] | ei[3] | ei[5] | ei[7] |
             ei[9] | ei[11] | ei[13] | ei[15]) == 0) ? 2 : 1;  // word stride
}

// ---------------- kernel 1: degree count + W fragment prep -----------------
__global__ void __launch_bounds__(256) countPrepKernel(const int* __restrict__ ei,
                                                       const float* __restrict__ W1,
                                                       const float* __restrict__ W2,
                                                       int E) {
    int blk = blockIdx.x;
    int t = threadIdx.x;
    if (blk < CSRBLK) {
        int e = blk * 256 + t;
        if (e < E) {
            int stride = detect64(ei);
            int dst = ei[(size_t)stride * (E + e)];
            if ((unsigned)dst < NNODES) atomicAdd(&d_cnt[dst], 1);
        }
    } else {
        int idx = (blk - CSRBLK) * 256 + t;   // 0..8191
        int kk = idx >> 9;
        int ct = (idx >> 5) & 15;
        int l = idx & 31;
        int k0 = kk * 8 + (l & 3);
        int n = ct * 8 + (l >> 2);
        uint2 v1, v2;
        v1.x = f2tf32(W1[k0 * HDIM + n]);
        v1.y = f2tf32(W1[(k0 + 4) * HDIM + n]);
        v2.x = f2tf32(W2[k0 * HDIM + n]);
        v2.y = f2tf32(W2[(k0 + 4) * HDIM + n]);
        d_w1f[idx] = v1;
        d_w2f[idx] = v2;
    }
}

// ---------------- kernel 2: CSR base offsets + dinv -------------------------
__global__ void baseKernel() {
    int n = blockIdx.x * blockDim.x + threadIdx.x;
    if (n < NNODES) {
        int c = d_cnt[n];
        int base = atomicAdd(&d_total, c);
        d_beg[n] = base;
        d_cur[n] = base;
        d_dinv[n] = rsqrtf((float)(c + 1));   // +1 for self loop
    }
}

// ---------------- tf32 MMA core over smem-staged A --------------------------
// xs[64][132]: 64 rows x 128 floats, pad 4 -> conflict-free fragment reads.
__device__ __forceinline__ void gemm_mma_smem(const float xs[64][132],
                                              const uint2* __restrict__ wf,
                                              unsigned* __restrict__ outp,
                                              int grbase, int w, int lane) {
    int tid = lane & 3;
    int gid = lane >> 2;
    int r0l = (w >> 1) * 16 + gid;
    int r1l = r0l + 8;
    int colbase = (w & 1) * 64;
    const uint2* wfh = wf + (w & 1) * 256;   // ct-half offset (8 tiles x 32)

    float c[8][4];
#pragma unroll
    for (int ct = 0; ct < 8; ct++)
#pragma unroll
        for (int j = 0; j < 4; j++) c[ct][j] = 0.f;

#pragma unroll 4
    for (int kk = 0; kk < 16; kk++) {
        int k0 = kk * 8 + tid;
        unsigned a0 = f2tf32(xs[r0l][k0]);
        unsigned a1 = f2tf32(xs[r1l][k0]);
        unsigned a2 = f2tf32(xs[r0l][k0 + 4]);
        unsigned a3 = f2tf32(xs[r1l][k0 + 4]);
        const uint2* wrow = wfh + kk * 512 + lane;
#pragma unroll
        for (int ct = 0; ct < 8; ct++) {
            uint2 b = wrow[ct * 32];
            mma_tf32(c[ct], a0, a1, a2, a3, b.x, b.y);
        }
    }

    int gr0 = grbase + r0l;
    int gr1 = grbase + r1l;
    float s0 = d_dinv[gr0 >> 3];
    float s1 = d_dinv[gr1 >> 3];
#pragma unroll
    for (int ct = 0; ct < 8; ct++) {
        int h = colbase + ct * 8 + tid * 2;
        outp[(size_t)gr0 * 64 + (h >> 1)] = f2_to_h2(c[ct][0] * s0, c[ct][1] * s0);
        outp[(size_t)gr1 * 64 + (h >> 1)] = f2_to_h2(c[ct][2] * s1, c[ct][3] * s1);
    }
}

// ---------------- kernel 3: GEMM1 (x @ W1) fused with CSR fill --------------
__global__ void __launch_bounds__(256) gemm1CsrKernel(const float4* __restrict__ x4,
                                                      const int* __restrict__ ei,
                                                      int E) {
    __shared__ float xs[64][132];
    int t = threadIdx.x;
    if (blockIdx.x < GEMMBLK) {
        int grbase = blockIdx.x * 64;
        // stage: x layout [b][n][f]; row r = n*8 + b
#pragma unroll
        for (int it = 0; it < 8; it++) {
            int e = it * 256 + t;
            int r = e >> 5, f4 = e & 31;
            int gr = grbase + r;
            float4 v = x4[((size_t)(gr & 7) * NNODES + (gr >> 3)) * 32 + f4];
            *(float4*)&xs[r][f4 * 4] = v;
        }
        __syncthreads();
        gemm_mma_smem(xs, d_w1f, (unsigned*)d_t1, grbase, t >> 5, t & 31);
    } else {
        int e = (blockIdx.x - GEMMBLK) * 256 + t;
        if (e < E) {
            int stride = detect64(ei);
            int src = ei[(size_t)stride * e];
            int dst = ei[(size_t)stride * (E + e)];
            if ((unsigned)src < NNODES && (unsigned)dst < NNODES) {
                int p = atomicAdd(&d_cur[dst], 1);
                if ((unsigned)p < EMAX) d_csr[p] = src * ROWB;  // byte offset
            }
        }
    }
}

// ---------------- kernel 5: GEMM2 (h1 @ W2) --------------------------------
__global__ void __launch_bounds__(256) gemm2Kernel() {
    __shared__ float xs[64][132];
    int t = threadIdx.x;
    int grbase = blockIdx.x * 64;
    const float4* h4 = (const float4*)d_h1;   // [r][128] contiguous
#pragma unroll
    for (int it = 0; it < 8; it++) {
        int e = it * 256 + t;
        int r = e >> 5, f4 = e & 31;
        *(float4*)&xs[r][f4 * 4] = h4[(size_t)(grbase + r) * 32 + f4];
    }
    __syncthreads();
    gemm_mma_smem(xs, d_w2f, (unsigned*)d_t2, grbase, t >> 5, t & 31);
}

// ---------------- aggregation: smem-staged offsets, uint2 gather, HADD2 -----
// Offsets pre-staged in smem -> gather LDGs issue back-to-back (high MLP).
__device__ __forceinline__ float4 agg_sum_staged(const uint2* __restrict__ tin,
                                                 int n, int c4,
                                                 const int* __restrict__ soff,
                                                 int cnt, int beg) {
    uint2 ps = tin[(size_t)n * BH4 + c4];          // self (prescaled)
    float2 sa = h2_to_f2(ps.x), sb = h2_to_f2(ps.y);
    float4 A = {sa.x, sa.y, sb.x, sb.y};
    float4 Bc = {0.f, 0.f, 0.f, 0.f};
    const char* basep = (const char*)(tin + c4);
    int m = (cnt < SMAX) ? cnt : SMAX;
    int e = 0;
    for (; e + 8 <= m; e += 8) {
        int o0 = soff[e + 0], o1 = soff[e + 1];
        int o2 = soff[e + 2], o3 = soff[e + 3];
        int o4 = soff[e + 4], o5 = soff[e + 5];
        int o6 = soff[e + 6], o7 = soff[e + 7];
        uint2 p0 = *(const uint2*)(basep + o0);
        uint2 p1 = *(const uint2*)(basep + o1);
        uint2 p2 = *(const uint2*)(basep + o2);
        uint2 p3 = *(const uint2*)(basep + o3);
        uint2 p4 = *(const uint2*)(basep + o4);
        uint2 p5 = *(const uint2*)(basep + o5);
        uint2 p6 = *(const uint2*)(basep + o6);
        uint2 p7 = *(const uint2*)(basep + o7);
        unsigned q0x = hadd2u(p0.x, p1.x), q0y = hadd2u(p0.y, p1.y);
        unsigned q1x = hadd2u(p2.x, p3.x), q1y = hadd2u(p2.y, p3.y);
        unsigned q2x = hadd2u(p4.x, p5.x), q2y = hadd2u(p4.y, p5.y);
        unsigned q3x = hadd2u(p6.x, p7.x), q3y = hadd2u(p6.y, p7.y);
        float2 f;
        f = h2_to_f2(q0x); A.x += f.x; A.y += f.y;
        f = h2_to_f2(q0y); A.z += f.x; A.w += f.y;
        f = h2_to_f2(q1x); Bc.x += f.x; Bc.y += f.y;
        f = h2_to_f2(q1y); Bc.z += f.x; Bc.w += f.y;
        f = h2_to_f2(q2x); A.x += f.x; A.y += f.y;
        f = h2_to_f2(q2y); A.z += f.x; A.w += f.y;
        f = h2_to_f2(q3x); Bc.x += f.x; Bc.y += f.y;
        f = h2_to_f2(q3y); Bc.z += f.x; Bc.w += f.y;
    }
    if (e + 4 <= m) {
        int o0 = soff[e + 0], o1 = soff[e + 1];
        int o2 = soff[e + 2], o3 = soff[e + 3];
        uint2 p0 = *(const uint2*)(basep + o0);
        uint2 p1 = *(const uint2*)(basep + o1);
        uint2 p2 = *(const uint2*)(basep + o2);
        uint2 p3 = *(const uint2*)(basep + o3);
        unsigned q0x = hadd2u(p0.x, p1.x), q0y = hadd2u(p0.y, p1.y);
        unsigned q1x = hadd2u(p2.x, p3.x), q1y = hadd2u(p2.y, p3.y);
        float2 f;
        f = h2_to_f2(q0x); A.x += f.x; A.y += f.y;
        f = h2_to_f2(q0y); A.z += f.x; A.w += f.y;
        f = h2_to_f2(q1x); Bc.x += f.x; Bc.y += f.y;
        f = h2_to_f2(q1y); Bc.z += f.x; Bc.w += f.y;
        e += 4;
    }
    if (e + 2 <= m) {
        int o0 = soff[e], o1 = soff[e + 1];
        uint2 p0 = *(const uint2*)(basep + o0);
        uint2 p1 = *(const uint2*)(basep + o1);
        unsigned qx = hadd2u(p0.x, p1.x), qy = hadd2u(p0.y, p1.y);
        float2 f;
        f = h2_to_f2(qx); A.x += f.x; A.y += f.y;
        f = h2_to_f2(qy); A.z += f.x; A.w += f.y;
        e += 2;
    }
    if (e < m) {
        uint2 p = *(const uint2*)(basep + soff[e]);
        float2 fa = h2_to_f2(p.x), fb = h2_to_f2(p.y);
        A.x += fa.x; A.y += fa.y; A.z += fb.x; A.w += fb.y;
    }
    for (int r = m; r < cnt; r++) {                // rare overflow path
        uint2 p = *(const uint2*)(basep + d_csr[beg + r]);
        float2 fa = h2_to_f2(p.x), fb = h2_to_f2(p.y);
        A.x += fa.x; A.y += fa.y; A.z += fb.x; A.w += fb.y;
    }
    float dn = d_dinv[n];
    float4 r;
    r.x = (A.x + Bc.x) * dn;
    r.y = (A.y + Bc.y) * dn;
    r.z = (A.z + Bc.z) * dn;
    r.w = (A.w + Bc.w) * dn;
    return r;
}

// kernel 4: one node per block; beg/cnt via uniform broadcast loads (no smem
// round-trip, single barrier), offsets staged to smem.
__global__ void __launch_bounds__(256) aggReluKernel(const float4* __restrict__ bias4) {
    __shared__ int soff[SMAX];
    int n = blockIdx.x;
    int t = threadIdx.x;
    int beg = d_beg[n];                     // uniform -> one broadcast LDG/warp
    int cnt = d_cnt[n];
    int m = (cnt < SMAX) ? cnt : SMAX;
    if (t < m) soff[t] = d_csr[beg + t];
    __syncthreads();

    float4 v = agg_sum_staged(d_t1, n, t, soff, cnt, beg);
    float4 bb = bias4[t & 31];
    v.x = fmaxf(v.x + bb.x, 0.f);
    v.y = fmaxf(v.y + bb.y, 0.f);
    v.z = fmaxf(v.z + bb.z, 0.f);
    v.w = fmaxf(v.w + bb.w, 0.f);
    d_h1[(size_t)n * BH4 + t] = v;          // fp32 GEMM2 input
}

// kernel 6: agg + LayerNorm; warp b owns row (n, b), lanes hold h=4*lane..+3.
// Tail restores the d_cnt/d_total == 0 invariant for the next replay.
__global__ void __launch_bounds__(256) aggLNKernel(const float4* __restrict__ bias4,
                                                   const float4* __restrict__ lnw4,
                                                   const float4* __restrict__ lnb4,
                                                   float4* __restrict__ out4) {
    __shared__ int soff[SMAX];
    int n = blockIdx.x;
    int t = threadIdx.x;
    int lane = t & 31;
    int b = t >> 5;
    int beg = d_beg[n];                     // uniform broadcast loads
    int cnt = d_cnt[n];
    int m = (cnt < SMAX) ? cnt : SMAX;
    if (t < m) soff[t] = d_csr[beg + t];
    __syncthreads();

    float4 v = agg_sum_staged(d_t2, n, t, soff, cnt, beg);
    float4 bb = bias4[lane];
    v.x += bb.x; v.y += bb.y; v.z += bb.z; v.w += bb.w;

    float s = (v.x + v.y) + (v.z + v.w);
#pragma unroll
    for (int off = 16; off > 0; off >>= 1) s += __shfl_xor_sync(0xffffffffu, s, off);
    float mean = s * (1.f / 128.f);

    float4 d;
    d.x = v.x - mean; d.y = v.y - mean; d.z = v.z - mean; d.w = v.w - mean;
    float s2 = (d.x * d.x + d.y * d.y) + (d.z * d.z + d.w * d.w);
#pragma unroll
    for (int off = 16; off > 0; off >>= 1) s2 += __shfl_xor_sync(0xffffffffu, s2, off);
    float rs = rsqrtf(s2 * (1.f / 128.f) + 1e-5f);

    float4 w = lnw4[lane];
    float4 bo = lnb4[lane];
    float4 r;
    r.x = d.x * rs * w.x + bo.x;
    r.y = d.y * rs * w.y + bo.y;
    r.z = d.z * rs * w.z + bo.z;
    r.w = d.w * rs * w.w + bo.w;
    out4[((size_t)b * NNODES + n) * 32 + lane] = r;

    // restore invariant (all reads of d_cnt[n] completed before staging sync)
    __syncthreads();
    if (t == 0) d_cnt[n] = 0;
    if (n == 0 && t == 1) d_total = 0;
}

// ---------------- launch ---------------------------------------------------
extern "C" void kernel_launch(void* const* d_in, const int* in_sizes, int n_in,
                              void* d_out, int out_size) {
    const float4* x4  = (const float4*)d_in[0];
    const int*    ei  = (const int*)d_in[1];     // int32 OR int64 (auto)
    const float*  W1  = (const float*)d_in[2];
    const float4* b1  = (const float4*)d_in[3];
    const float*  W2  = (const float*)d_in[4];
    const float4* b2  = (const float4*)d_in[5];
    const float4* lnw = (const float4*)d_in[6];
    const float4* lnb = (const float4*)d_in[7];
    float4*       out = (float4*)d_out;

    int E = in_sizes[1] / 2;
    if (E > EMAX) E = EMAX;

    countPrepKernel<<<CSRBLK + 32, 256>>>(ei, W1, W2, E);
    baseKernel<<<(NNODES + 255) / 256, 256>>>();
    gemm1CsrKernel<<<GEMMBLK + CSRBLK, 256>>>(x4, ei, E);
    aggReluKernel<<<NNODES, 256>>>(b1);
    gemm2Kernel<<<GEMMBLK, 256>>>();
    aggLNKernel<<<NNODES, 256>>>(b2, lnw, lnb, out);
}

// round 17
// speedup vs baseline: 1.6073x; 1.1806x over previous
#include <cuda_runtime.h>
#include <cuda_fp16.h>

// GNNEncoder: B=8, N=10000, F_IN=128, H=128, E=160000
#define NB     8
#define NNODES 10000
#define HDIM   128
#define BH     (NB * HDIM)        // 1024
#define BH4    (BH / 4)           // 256 uint2 (4 halves) per node row
#define ROWB   2048               // node row byte stride (BH4 * 8)
#define EMAX   160000
#define ROWS   (NNODES * NB)      // 80000 gemm rows (node-major: r = n*8+b)
#define GEMMBLK 1250              // ROWS / 64
#define CSRBLK  625               // EMAX / 256
#define SMAX   256                // staged edge offsets per node

// ---------------- device scratch -------------------------------------------
// Invariant: d_cnt[] == 0 and d_total == 0 at entry of every kernel_launch
// (static init supplies the first call; aggLN's tail restores it each call).
__device__ uint2  d_t1[NNODES * BH4];   // fp16 x4, dinv-prescaled gather rows
__device__ uint2  d_h1[NNODES * BH4];   // fp16 relu(agg1+b1): GEMM2 input
__device__ uint2  d_t2[NNODES * BH4];   // fp16 x4, dinv-prescaled
__device__ __align__(16) uint2 d_w1h[8 * 16 * 32];  // W fp16 frag [kk][ct][lane]
__device__ __align__(16) uint2 d_w2h[8 * 16 * 32];
__device__ int    d_cnt[NNODES];
__device__ int    d_beg[NNODES];
__device__ int    d_cur[NNODES];
__device__ float  d_dinv[NNODES];
__device__ int    d_csr[EMAX];          // holds src * ROWB (byte offsets)
__device__ int    d_total;

// ---------------- helpers --------------------------------------------------
__device__ __forceinline__ unsigned f2_to_h2(float lo, float hi) {
    unsigned r;
    asm("cvt.rn.f16x2.f32 %0, %1, %2;" : "=r"(r) : "f"(hi), "f"(lo));
    return r;
}
__device__ __forceinline__ float2 h2_to_f2(unsigned u) {
    __half2 h = *reinterpret_cast<__half2*>(&u);
    return __half22float2(h);
}
__device__ __forceinline__ unsigned hadd2u(unsigned a, unsigned b) {
    __half2 ha = *reinterpret_cast<__half2*>(&a);
    __half2 hb = *reinterpret_cast<__half2*>(&b);
    __half2 hr = __hadd2(ha, hb);
    return *reinterpret_cast<unsigned*>(&hr);
}
__device__ __forceinline__ void mma_f16(float* c, unsigned a0, unsigned a1,
                                        unsigned a2, unsigned a3,
                                        unsigned b0, unsigned b1) {
    asm("mma.sync.aligned.m16n8k16.row.col.f32.f16.f16.f32 "
        "{%0,%1,%2,%3}, {%4,%5,%6,%7}, {%8,%9}, {%0,%1,%2,%3};"
        : "+f"(c[0]), "+f"(c[1]), "+f"(c[2]), "+f"(c[3])
        : "r"(a0), "r"(a1), "r"(a2), "r"(a3), "r"(b0), "r"(b1));
}
// int64 buffers hold values < 2^31 -> odd 32-bit words are all zero.
__device__ __forceinline__ int detect64(const int* __restrict__ ei) {
    return ((ei[1] | ei[3] | ei[5] | ei[7] |
             ei[9] | ei[11] | ei[13] | ei[15]) == 0) ? 2 : 1;  // word stride
}

// ---------------- kernel 1: degree count + W fragment prep -----------------
// W frag (m16n8k16 B operand, col-major): for kk,ct,lane (tid=l&3, gid=l>>2):
//   b0 = (W[k0][n], W[k0+1][n]),  b1 = (W[k0+8][n], W[k0+9][n])
//   k0 = kk*16 + tid*2,  n = ct*8 + gid
__global__ void __launch_bounds__(256) countPrepKernel(const int* __restrict__ ei,
                                                       const float* __restrict__ W1,
                                                       const float* __restrict__ W2,
                                                       int E) {
    int blk = blockIdx.x;
    int t = threadIdx.x;
    if (blk < CSRBLK) {
        int e = blk * 256 + t;
        if (e < E) {
            int stride = detect64(ei);
            int dst = ei[(size_t)stride * (E + e)];
            if ((unsigned)dst < NNODES) atomicAdd(&d_cnt[dst], 1);
        }
    } else {
        int idx = (blk - CSRBLK) * 256 + t;   // 0..4095
        if (idx < 8 * 16 * 32) {
            int kk = idx >> 9;                // 0..7
            int ct = (idx >> 5) & 15;
            int l = idx & 31;
            int k0 = kk * 16 + (l & 3) * 2;
            int n = ct * 8 + (l >> 2);
            uint2 v1, v2;
            v1.x = f2_to_h2(W1[k0 * HDIM + n], W1[(k0 + 1) * HDIM + n]);
            v1.y = f2_to_h2(W1[(k0 + 8) * HDIM + n], W1[(k0 + 9) * HDIM + n]);
            v2.x = f2_to_h2(W2[k0 * HDIM + n], W2[(k0 + 1) * HDIM + n]);
            v2.y = f2_to_h2(W2[(k0 + 8) * HDIM + n], W2[(k0 + 9) * HDIM + n]);
            d_w1h[idx] = v1;
            d_w2h[idx] = v2;
        }
    }
}

// ---------------- kernel 2: CSR base offsets + dinv -------------------------
__global__ void baseKernel() {
    int n = blockIdx.x * blockDim.x + threadIdx.x;
    if (n < NNODES) {
        int c = d_cnt[n];
        int base = atomicAdd(&d_total, c);
        d_beg[n] = base;
        d_cur[n] = base;
        d_dinv[n] = rsqrtf((float)(c + 1));   // +1 for self loop
    }
}

// ---------------- fp16 MMA core over smem-staged A --------------------------
// xs[64][68]: 64 rows x 64 h2 words (128 halves), pad 4 words ->
// bank(68r + w) = (4r + w) % 32: conflict-free for the fragment pattern.
__device__ __forceinline__ void gemm_mma_smem(const unsigned xs[64][68],
                                              const uint2* __restrict__ wf,
                                              unsigned* __restrict__ outp,
                                              int grbase, int w, int lane) {
    int tid = lane & 3;
    int gid = lane >> 2;
    int r0l = (w >> 1) * 16 + gid;
    int r1l = r0l + 8;
    int colbase = (w & 1) * 64;
    const uint2* wfh = wf + (w & 1) * 256;   // ct-half offset (8 tiles x 32)

    float c[8][4];
#pragma unroll
    for (int ct = 0; ct < 8; ct++)
#pragma unroll
        for (int j = 0; j < 4; j++) c[ct][j] = 0.f;

#pragma unroll
    for (int kk = 0; kk < 8; kk++) {
        int w0 = kk * 8 + tid;
        unsigned a0 = xs[r0l][w0];
        unsigned a1 = xs[r1l][w0];
        unsigned a2 = xs[r0l][w0 + 4];
        unsigned a3 = xs[r1l][w0 + 4];
        const uint2* wrow = wfh + kk * 512 + lane;   // kk stride = 16*32
#pragma unroll
        for (int ct = 0; ct < 8; ct++) {
            uint2 b = wrow[ct * 32];
            mma_f16(c[ct], a0, a1, a2, a3, b.x, b.y);
        }
    }

    int gr0 = grbase + r0l;
    int gr1 = grbase + r1l;
    float s0 = d_dinv[gr0 >> 3];
    float s1 = d_dinv[gr1 >> 3];
#pragma unroll
    for (int ct = 0; ct < 8; ct++) {
        int h = colbase + ct * 8 + tid * 2;
        outp[(size_t)gr0 * 64 + (h >> 1)] = f2_to_h2(c[ct][0] * s0, c[ct][1] * s0);
        outp[(size_t)gr1 * 64 + (h >> 1)] = f2_to_h2(c[ct][2] * s1, c[ct][3] * s1);
    }
}

// ---------------- kernel 3: GEMM1 (x @ W1) fused with CSR fill --------------
__global__ void __launch_bounds__(256) gemm1CsrKernel(const float4* __restrict__ x4,
                                                      const int* __restrict__ ei,
                                                      int E) {
    __shared__ unsigned xs[64][68];
    int t = threadIdx.x;
    if (blockIdx.x < GEMMBLK) {
        int grbase = blockIdx.x * 64;
        // stage: x layout [b][n][f]; row r = n*8 + b; convert fp32 -> h2
#pragma unroll
        for (int it = 0; it < 8; it++) {
            int e = it * 256 + t;
            int r = e >> 5, f4 = e & 31;
            int gr = grbase + r;
            float4 v = x4[((size_t)(gr & 7) * NNODES + (gr >> 3)) * 32 + f4];
            uint2 hv;
            hv.x = f2_to_h2(v.x, v.y);
            hv.y = f2_to_h2(v.z, v.w);
            *(uint2*)&xs[r][f4 * 2] = hv;
        }
        __syncthreads();
        gemm_mma_smem(xs, d_w1h, (unsigned*)d_t1, grbase, t >> 5, t & 31);
    } else {
        int e = (blockIdx.x - GEMMBLK) * 256 + t;
        if (e < E) {
            int stride = detect64(ei);
            int src = ei[(size_t)stride * e];
            int dst = ei[(size_t)stride * (E + e)];
            if ((unsigned)src < NNODES && (unsigned)dst < NNODES) {
                int p = atomicAdd(&d_cur[dst], 1);
                if ((unsigned)p < EMAX) d_csr[p] = src * ROWB;  // byte offset
            }
        }
    }
}

// ---------------- kernel 5: GEMM2 (h1 @ W2) --------------------------------
__global__ void __launch_bounds__(256) gemm2Kernel() {
    __shared__ unsigned xs[64][68];
    int t = threadIdx.x;
    int grbase = blockIdx.x * 64;
#pragma unroll
    for (int it = 0; it < 8; it++) {
        int e = it * 256 + t;
        int r = e >> 5, u = e & 31;          // 32 uint2 per fp16 row
        *(uint2*)&xs[r][u * 2] = d_h1[(size_t)(grbase + r) * 32 + u];
    }
    __syncthreads();
    gemm_mma_smem(xs, d_w2h, (unsigned*)d_t2, grbase, t >> 5, t & 31);
}

// ---------------- aggregation: smem-staged offsets, uint2 gather, HADD2 -----
__device__ __forceinline__ float4 agg_sum_staged(const uint2* __restrict__ tin,
                                                 int n, int c4,
                                                 const int* __restrict__ soff,
                                                 int cnt, int beg) {
    uint2 ps = tin[(size_t)n * BH4 + c4];          // self (prescaled)
    float2 sa = h2_to_f2(ps.x), sb = h2_to_f2(ps.y);
    float4 A = {sa.x, sa.y, sb.x, sb.y};
    float4 Bc = {0.f, 0.f, 0.f, 0.f};
    const char* basep = (const char*)(tin + c4);
    int m = (cnt < SMAX) ? cnt : SMAX;
    int e = 0;
    for (; e + 8 <= m; e += 8) {
        int o0 = soff[e + 0], o1 = soff[e + 1];
        int o2 = soff[e + 2], o3 = soff[e + 3];
        int o4 = soff[e + 4], o5 = soff[e + 5];
        int o6 = soff[e + 6], o7 = soff[e + 7];
        uint2 p0 = *(const uint2*)(basep + o0);
        uint2 p1 = *(const uint2*)(basep + o1);
        uint2 p2 = *(const uint2*)(basep + o2);
        uint2 p3 = *(const uint2*)(basep + o3);
        uint2 p4 = *(const uint2*)(basep + o4);
        uint2 p5 = *(const uint2*)(basep + o5);
        uint2 p6 = *(const uint2*)(basep + o6);
        uint2 p7 = *(const uint2*)(basep + o7);
        unsigned q0x = hadd2u(p0.x, p1.x), q0y = hadd2u(p0.y, p1.y);
        unsigned q1x = hadd2u(p2.x, p3.x), q1y = hadd2u(p2.y, p3.y);
        unsigned q2x = hadd2u(p4.x, p5.x), q2y = hadd2u(p4.y, p5.y);
        unsigned q3x = hadd2u(p6.x, p7.x), q3y = hadd2u(p6.y, p7.y);
        float2 f;
        f = h2_to_f2(q0x); A.x += f.x; A.y += f.y;
        f = h2_to_f2(q0y); A.z += f.x; A.w += f.y;
        f = h2_to_f2(q1x); Bc.x += f.x; Bc.y += f.y;
        f = h2_to_f2(q1y); Bc.z += f.x; Bc.w += f.y;
        f = h2_to_f2(q2x); A.x += f.x; A.y += f.y;
        f = h2_to_f2(q2y); A.z += f.x; A.w += f.y;
        f = h2_to_f2(q3x); Bc.x += f.x; Bc.y += f.y;
        f = h2_to_f2(q3y); Bc.z += f.x; Bc.w += f.y;
    }
    if (e + 4 <= m) {
        int o0 = soff[e + 0], o1 = soff[e + 1];
        int o2 = soff[e + 2], o3 = soff[e + 3];
        uint2 p0 = *(const uint2*)(basep + o0);
        uint2 p1 = *(const uint2*)(basep + o1);
        uint2 p2 = *(const uint2*)(basep + o2);
        uint2 p3 = *(const uint2*)(basep + o3);
        unsigned q0x = hadd2u(p0.x, p1.x), q0y = hadd2u(p0.y, p1.y);
        unsigned q1x = hadd2u(p2.x, p3.x), q1y = hadd2u(p2.y, p3.y);
        float2 f;
        f = h2_to_f2(q0x); A.x += f.x; A.y += f.y;
        f = h2_to_f2(q0y); A.z += f.x; A.w += f.y;
        f = h2_to_f2(q1x); Bc.x += f.x; Bc.y += f.y;
        f = h2_to_f2(q1y); Bc.z += f.x; Bc.w += f.y;
        e += 4;
    }
    if (e + 2 <= m) {
        int o0 = soff[e], o1 = soff[e + 1];
        uint2 p0 = *(const uint2*)(basep + o0);
        uint2 p1 = *(const uint2*)(basep + o1);
        unsigned qx = hadd2u(p0.x, p1.x), qy = hadd2u(p0.y, p1.y);
        float2 f;
        f = h2_to_f2(qx); A.x += f.x; A.y += f.y;
        f = h2_to_f2(qy); A.z += f.x; A.w += f.y;
        e += 2;
    }
    if (e < m) {
        uint2 p = *(const uint2*)(basep + soff[e]);
        float2 fa = h2_to_f2(p.x), fb = h2_to_f2(p.y);
        A.x += fa.x; A.y += fa.y; A.z += fb.x; A.w += fb.y;
    }
    for (int r = m; r < cnt; r++) {                // rare overflow path
        uint2 p = *(const uint2*)(basep + d_csr[beg + r]);
        float2 fa = h2_to_f2(p.x), fb = h2_to_f2(p.y);
        A.x += fa.x; A.y += fa.y; A.z += fb.x; A.w += fb.y;
    }
    float dn = d_dinv[n];
    float4 r;
    r.x = (A.x + Bc.x) * dn;
    r.y = (A.y + Bc.y) * dn;
    r.z = (A.z + Bc.z) * dn;
    r.w = (A.w + Bc.w) * dn;
    return r;
}

// kernel 4: one node per block; beg/cnt via uniform broadcast loads.
// Writes h1 as fp16 (same 10-bit mantissa GEMM2 would keep anyway).
__global__ void __launch_bounds__(256) aggReluKernel(const float4* __restrict__ bias4) {
    __shared__ int soff[SMAX];
    int n = blockIdx.x;
    int t = threadIdx.x;
    int beg = d_beg[n];                     // uniform -> one broadcast LDG/warp
    int cnt = d_cnt[n];
    int m = (cnt < SMAX) ? cnt : SMAX;
    if (t < m) soff[t] = d_csr[beg + t];
    __syncthreads();

    float4 v = agg_sum_staged(d_t1, n, t, soff, cnt, beg);
    float4 bb = bias4[t & 31];
    v.x = fmaxf(v.x + bb.x, 0.f);
    v.y = fmaxf(v.y + bb.y, 0.f);
    v.z = fmaxf(v.z + bb.z, 0.f);
    v.w = fmaxf(v.w + bb.w, 0.f);
    uint2 hv;
    hv.x = f2_to_h2(v.x, v.y);
    hv.y = f2_to_h2(v.z, v.w);
    // row r = n*8 + b (b = t>>5), uint2 index within row = t&31
    d_h1[((size_t)n * 8 + (t >> 5)) * 32 + (t & 31)] = hv;
}

// kernel 6: agg + LayerNorm; warp b owns row (n, b), lanes hold h=4*lane..+3.
// Tail restores the d_cnt/d_total == 0 invariant for the next replay.
__global__ void __launch_bounds__(256) aggLNKernel(const float4* __restrict__ bias4,
                                                   const float4* __restrict__ lnw4,
                                                   const float4* __restrict__ lnb4,
                                                   float4* __restrict__ out4) {
    __shared__ int soff[SMAX];
    int n = blockIdx.x;
    int t = threadIdx.x;
    int lane = t & 31;
    int b = t >> 5;
    int beg = d_beg[n];                     // uniform broadcast loads
    int cnt = d_cnt[n];
    int m = (cnt < SMAX) ? cnt : SMAX;
    if (t < m) soff[t] = d_csr[beg + t];
    __syncthreads();

    float4 v = agg_sum_staged(d_t2, n, t, soff, cnt, beg);
    float4 bb = bias4[lane];
    v.x += bb.x; v.y += bb.y; v.z += bb.z; v.w += bb.w;

    float s = (v.x + v.y) + (v.z + v.w);
#pragma unroll
    for (int off = 16; off > 0; off >>= 1) s += __shfl_xor_sync(0xffffffffu, s, off);
    float mean = s * (1.f / 128.f);

    float4 d;
    d.x = v.x - mean; d.y = v.y - mean; d.z = v.z - mean; d.w = v.w - mean;
    float s2 = (d.x * d.x + d.y * d.y) + (d.z * d.z + d.w * d.w);
#pragma unroll
    for (int off = 16; off > 0; off >>= 1) s2 += __shfl_xor_sync(0xffffffffu, s2, off);
    float rs = rsqrtf(s2 * (1.f / 128.f) + 1e-5f);

    float4 w = lnw4[lane];
    float4 bo = lnb4[lane];
    float4 r;
    r.x = d.x * rs * w.x + bo.x;
    r.y = d.y * rs * w.y + bo.y;
    r.z = d.z * rs * w.z + bo.z;
    r.w = d.w * rs * w.w + bo.w;
    out4[((size_t)b * NNODES + n) * 32 + lane] = r;

    // restore invariant (all reads of d_cnt[n] completed before staging sync)
    __syncthreads();
    if (t == 0) d_cnt[n] = 0;
    if (n == 0 && t == 1) d_total = 0;
}

// ---------------- launch ---------------------------------------------------
extern "C" void kernel_launch(void* const* d_in, const int* in_sizes, int n_in,
                              void* d_out, int out_size) {
    const float4* x4  = (const float4*)d_in[0];
    const int*    ei  = (const int*)d_in[1];     // int32 OR int64 (auto)
    const float*  W1  = (const float*)d_in[2];
    const float4* b1  = (const float4*)d_in[3];
    const float*  W2  = (const float*)d_in[4];
    const float4* b2  = (const float4*)d_in[5];
    const float4* lnw = (const float4*)d_in[6];
    const float4* lnb = (const float4*)d_in[7];
    float4*       out = (float4*)d_out;

    int E = in_sizes[1] / 2;
    if (E > EMAX) E = EMAX;

    countPrepKernel<<<CSRBLK + 16, 256>>>(ei, W1, W2, E);
    baseKernel<<<(NNODES + 255) / 256, 256>>>();
    gemm1CsrKernel<<<GEMMBLK + CSRBLK, 256>>>(x4, ei, E);
    aggReluKernel<<<NNODES, 256>>>(b1);
    gemm2Kernel<<<GEMMBLK, 256>>>();
    aggLNKernel<<<NNODES, 256>>>(b2, lnw, lnb, out);
}